// round 14
// baseline (speedup 1.0000x reference)
#include <cuda_runtime.h>
#include <cuda_fp16.h>
#include <cstdint>

// ---------------------------------------------------------------------------
// SmallMLP_INR: fused 6-layer MLP, base-target ISA (compute_103-safe).
// EXPERIMENT: fp16-accumulate mma.sync (m16n8k16.f16) in k32 windows,
// promoted into fp32 shadow accumulators every 2 ksteps — tests whether the
// legacy HMMA pipe runs f16-accum at 2x the f32-accum rate on sm_103.
// Persistent CTAs (R13 win) + flat cross-tile cp.async ring, 512 threads,
// 16 warps of 32M x 64N tiles (register budget for dual accumulators).
// ---------------------------------------------------------------------------

#define THREADS 512
#define TILE_M  128
#define KDIM    256
#define NDIM    256

#define A_STRIDE 264       // halves; 528B rows -> ldmatrix conflict-free
#define B_STRIDE 72        // halves; 144B rows -> ldmatrix conflict-free
#define SLOT_BYTES 36864   // 256 * 72 * 2

// SMEM layout (bytes)
#define SM_W1    0        // 512 f32
#define SM_B1    2048
#define SM_B2    3072
#define SM_B3    4096
#define SM_B4    5120
#define SM_B5    6144
#define SM_W6    7168
#define SM_B6    8192
#define SM_PART  8208     // 4*128 f32 = 2048
#define SM_A     10496    // 128*264*2 = 67584
#define SM_RING  78080    // 4 * 36864 = 147456
#define SMEM_TOTAL 225536

// Pre-transposed fp16 weights: g_WtH[l][n*256 + k] = (half)W_{l+2}[k][n]
__device__ __half g_WtH[4][KDIM * NDIM];

// ---------------------------------------------------------------------------
__device__ __forceinline__ uint32_t smem_u32(const void* p) {
    uint32_t a;
    asm("{ .reg .u64 t; cvta.to.shared.u64 t, %1; cvt.u32.u64 %0, t; }" : "=r"(a) : "l"(p));
    return a;
}

// f16-accum mma, C = 0 (window start)
__device__ __forceinline__ void mma_h0(uint32_t* d, const uint32_t* a, const uint32_t* b) {
    asm volatile(
        "mma.sync.aligned.m16n8k16.row.col.f16.f16.f16.f16 "
        "{%0,%1}, {%2,%3,%4,%5}, {%6,%7}, {%8,%9};\n"
        : "=r"(d[0]), "=r"(d[1])
        : "r"(a[0]), "r"(a[1]), "r"(a[2]), "r"(a[3]),
          "r"(b[0]), "r"(b[1]), "r"(0u), "r"(0u));
}

// f16-accum mma, C = D (window continue)
__device__ __forceinline__ void mma_hacc(uint32_t* d, const uint32_t* a, const uint32_t* b) {
    asm volatile(
        "mma.sync.aligned.m16n8k16.row.col.f16.f16.f16.f16 "
        "{%0,%1}, {%2,%3,%4,%5}, {%6,%7}, {%0,%1};\n"
        : "+r"(d[0]), "+r"(d[1])
        : "r"(a[0]), "r"(a[1]), "r"(a[2]), "r"(a[3]), "r"(b[0]), "r"(b[1]));
}

#define LDMATRIX_X4(r0, r1, r2, r3, addr) \
    asm volatile("ldmatrix.sync.aligned.m8n8.x4.shared.b16 {%0,%1,%2,%3}, [%4];" \
                 : "=r"(r0), "=r"(r1), "=r"(r2), "=r"(r3) : "r"(addr))

__device__ __forceinline__ void cp_async16(uint32_t dst, const void* src) {
    asm volatile("cp.async.cg.shared.global [%0], [%1], 16;" :: "r"(dst), "l"(src) : "memory");
}
__device__ __forceinline__ void cp_commit() { asm volatile("cp.async.commit_group;" ::: "memory"); }
__device__ __forceinline__ void cp_wait2()  { asm volatile("cp.async.wait_group 2;" ::: "memory"); }
__device__ __forceinline__ void cp_wait1()  { asm volatile("cp.async.wait_group 1;" ::: "memory"); }
__device__ __forceinline__ void cp_wait0()  { asm volatile("cp.async.wait_group 0;" ::: "memory"); }

// CTA-wide (512 thr): one 256x64 weight chunk (32KB) into a ring slot.
__device__ __forceinline__ void load_chunk(uint32_t slot, const __half* Wt,
                                           int c, int tid) {
    const int row = tid >> 1;
    const int ko  = (tid & 1) * 32;
    uint32_t dst = slot + (uint32_t)row * (B_STRIDE * 2) + (uint32_t)ko * 2;
    const __half* src = Wt + (size_t)row * KDIM + c * 64 + ko;
#pragma unroll
    for (int j = 0; j < 4; j++)
        cp_async16(dst + j * 16, src + j * 8);
    cp_commit();
}

// ---------------------------------------------------------------------------
// weight pre-transpose + fp16 round
// ---------------------------------------------------------------------------
__global__ void transpose_w_kernel(const float* __restrict__ W2, const float* __restrict__ W3,
                                   const float* __restrict__ W4, const float* __restrict__ W5) {
    __shared__ float t[32][33];
    const float* W = (blockIdx.z == 0) ? W2 : (blockIdx.z == 1) ? W3
                   : (blockIdx.z == 2) ? W4 : W5;
    const int nb = blockIdx.x * 32, kb = blockIdx.y * 32;
    const int tx = threadIdx.x, ty = threadIdx.y;
#pragma unroll
    for (int i = 0; i < 32; i += 8)
        t[ty + i][tx] = W[(size_t)(kb + ty + i) * 256 + (nb + tx)];
    __syncthreads();
    __half* dst = g_WtH[blockIdx.z];
#pragma unroll
    for (int i = 0; i < 32; i += 8)
        dst[(size_t)(nb + ty + i) * 256 + (kb + tx)] = __float2half_rn(t[tx][ty + i]);
}

// ---------------------------------------------------------------------------
// main persistent kernel: CTA grid-strides over 128-row tiles;
// 16 warps of 32M x 64N; f16-accum mma with k32 promotion windows
// ---------------------------------------------------------------------------
__global__ void __launch_bounds__(THREADS, 1) mlp_kernel(
    const float* __restrict__ coords,
    const float* __restrict__ W1, const float* __restrict__ b1,
    const float* __restrict__ b2, const float* __restrict__ b3,
    const float* __restrict__ b4, const float* __restrict__ b5,
    const float* __restrict__ W6, const float* __restrict__ b6,
    float* __restrict__ out, int ntiles) {
    extern __shared__ __align__(128) char smem[];
    const uint32_t sb = smem_u32(smem);
    const int tid = threadIdx.x;
    const int wid = tid >> 5;
    const int lid = tid & 31;
    const int g = lid >> 2;
    const int t = lid & 3;
    const int mrow = (wid & 3) * 32;      // 4 M-slots of 32 rows
    const int ncol = (wid >> 2) * 64;     // 4 N-slots of 64 cols

    float* sW1 = (float*)(smem + SM_W1);
    float* sB1 = (float*)(smem + SM_B1);
    float* sB2 = (float*)(smem + SM_B2);
    float* sB3 = (float*)(smem + SM_B3);
    float* sB4 = (float*)(smem + SM_B4);
    float* sB5 = (float*)(smem + SM_B5);
    float* sW6 = (float*)(smem + SM_W6);
    float* sB6 = (float*)(smem + SM_B6);
    float* sPart = (float*)(smem + SM_PART);
    __half* sA = (__half*)(smem + SM_A);
    const uint32_t rb = sb + SM_RING;

    // stage small params
    if (tid < 256) {
        sW1[tid]       = W1[tid];
        sW1[tid + 256] = W1[tid + 256];
        sB1[tid] = b1[tid];
        sB2[tid] = b2[tid];
        sB3[tid] = b3[tid];
        sB4[tid] = b4[tid];
        sB5[tid] = b5[tid];
        sW6[tid] = W6[tid];
    }
    if (tid == 0) sB6[0] = b6[0];

    // prologue: prefetch chunks 0..2 of layer 2 (slots 0..2)
    load_chunk(rb,                  g_WtH[0], 0, tid);
    load_chunk(rb + SLOT_BYTES,     g_WtH[0], 1, tid);
    load_chunk(rb + 2 * SLOT_BYTES, g_WtH[0], 2, tid);

    __syncthreads();

    // ldmatrix lane-address bases
    const uint32_t aA = sb + SM_A +
        (uint32_t)(((mrow + (lid & 15)) * A_STRIDE + ((lid & 16) ? 8 : 0)) * 2);
    const uint32_t bOff =
        (uint32_t)((ncol + (lid & 7) + ((lid & 16) ? 8 : 0)) * B_STRIDE * 2 +
                   ((lid & 8) ? 16 : 0));

    const int stride = gridDim.x;

#pragma unroll 1
    for (int tile = blockIdx.x; tile < ntiles; tile += stride) {
        const bool lastT = (tile + stride >= ntiles);
        const int row_base = tile * TILE_M;

        // ---- Layer 1 (fan-in 2, FFMA) -> sA (fp16) ----
        {
            const int row = tid >> 2;
            const int j0  = (tid & 3) * 64;
            const float2 c = *(const float2*)(coords + 2 * (size_t)(row_base + row));
            __half* dst = sA + (size_t)row * A_STRIDE;
#pragma unroll
            for (int j = 0; j < 64; j += 2) {
                const int jj = j0 + j;
                float v0 = fmaxf(fmaf(c.x, sW1[jj + 0], fmaf(c.y, sW1[256 + jj + 0], sB1[jj + 0])), 0.f);
                float v1 = fmaxf(fmaf(c.x, sW1[jj + 1], fmaf(c.y, sW1[256 + jj + 1], sB1[jj + 1])), 0.f);
                *(__half2*)(dst + jj) = __floats2half2_rn(v0, v1);
            }
        }
        // ordered by the first chunk barrier below

        // ---- Layers 2..5 ----
#pragma unroll 1
        for (int l = 0; l < 4; l++) {
            float acc[2][8][4];                 // fp32 shadow
#pragma unroll
            for (int i = 0; i < 2; i++)
#pragma unroll
                for (int j = 0; j < 8; j++)
#pragma unroll
                    for (int c = 0; c < 4; c++) acc[i][j][c] = 0.f;

            const bool drain = lastT && (l == 3);
#pragma unroll
            for (int c = 0; c < 4; c++) {
                if (drain && c == 2)      cp_wait1();
                else if (drain && c == 3) cp_wait0();
                else                      cp_wait2();
                __syncthreads();

                const uint32_t bB = rb + (uint32_t)c * SLOT_BYTES + bOff;
                uint32_t acc16[2][8][2];        // f16x2 window accumulators

#pragma unroll
                for (int ks = 0; ks < 4; ks++) {
                    const int k0 = c * 64 + ks * 16;   // global k (halves)
                    uint32_t a[2][4];
#pragma unroll
                    for (int i = 0; i < 2; i++) {
                        const uint32_t addr = aA + (uint32_t)(i * 16 * A_STRIDE + k0) * 2;
                        LDMATRIX_X4(a[i][0], a[i][1], a[i][2], a[i][3], addr);
                    }
#pragma unroll
                    for (int jp = 0; jp < 4; jp++) {
                        uint32_t b[4];
                        const uint32_t addr = bB + (uint32_t)(jp * 16 * B_STRIDE + ks * 16) * 2;
                        LDMATRIX_X4(b[0], b[1], b[2], b[3], addr);
#pragma unroll
                        for (int i = 0; i < 2; i++)
#pragma unroll
                            for (int jj = 0; jj < 2; jj++) {
                                const int j = 2 * jp + jj;
                                if ((ks & 1) == 0)
                                    mma_h0(acc16[i][j], a[i], b + 2 * jj);
                                else
                                    mma_hacc(acc16[i][j], a[i], b + 2 * jj);
                            }
                    }
                    if (ks & 1) {
                        // promote k32 window into fp32 shadow
#pragma unroll
                        for (int i = 0; i < 2; i++)
#pragma unroll
                            for (int j = 0; j < 8; j++) {
                                float2 lo = __half22float2(
                                    *reinterpret_cast<__half2*>(&acc16[i][j][0]));
                                float2 hi = __half22float2(
                                    *reinterpret_cast<__half2*>(&acc16[i][j][1]));
                                acc[i][j][0] += lo.x;
                                acc[i][j][1] += lo.y;
                                acc[i][j][2] += hi.x;
                                acc[i][j][3] += hi.y;
                            }
                    }
                }

                // prefetch flat chunk G+3 into slot (c+3)&3 (freed by G-1;
                // safe: all warps passed this chunk's barrier)
                if (!(drain && c >= 1)) {
                    const int cq = (c + 3) & 3;
                    const int lgq = ((l * 4 + c + 3) >> 2) & 3;
                    load_chunk(rb + (uint32_t)cq * SLOT_BYTES, g_WtH[lgq], cq, tid);
                }
            }

            __syncthreads();   // all warps done reading sA

            if (l < 3) {
                // epilogue: sA <- (half)relu(D + bias) for this warp's 32x64 tile
                const float* bias = (l == 0) ? sB2 : (l == 1) ? sB3 : sB4;
#pragma unroll
                for (int j = 0; j < 8; j++) {
                    const int col = ncol + 8 * j + 2 * t;
                    const float bs0 = bias[col], bs1 = bias[col + 1];
#pragma unroll
                    for (int i = 0; i < 2; i++) {
                        const int row = mrow + 16 * i + g;
                        *(__half2*)(sA + (size_t)row * A_STRIDE + col) =
                            __floats2half2_rn(fmaxf(acc[i][j][0] + bs0, 0.f),
                                              fmaxf(acc[i][j][1] + bs1, 0.f));
                        *(__half2*)(sA + (size_t)(row + 8) * A_STRIDE + col) =
                            __floats2half2_rn(fmaxf(acc[i][j][2] + bs0, 0.f),
                                              fmaxf(acc[i][j][3] + bs1, 0.f));
                    }
                }
                // next chunk's __syncthreads orders these writes before reads
            } else {
                // ---- Layer 6: out = relu(D + b5) . W6 + b6 ----
                float r0[2] = {0.f, 0.f};
                float r1[2] = {0.f, 0.f};
#pragma unroll
                for (int j = 0; j < 8; j++) {
                    const int col = ncol + 8 * j + 2 * t;
                    const float w0 = sW6[col], w1 = sW6[col + 1];
                    const float s0 = sB5[col], s1 = sB5[col + 1];
#pragma unroll
                    for (int i = 0; i < 2; i++) {
                        r0[i] = fmaf(fmaxf(acc[i][j][0] + s0, 0.f), w0, r0[i]);
                        r0[i] = fmaf(fmaxf(acc[i][j][1] + s1, 0.f), w1, r0[i]);
                        r1[i] = fmaf(fmaxf(acc[i][j][2] + s0, 0.f), w0, r1[i]);
                        r1[i] = fmaf(fmaxf(acc[i][j][3] + s1, 0.f), w1, r1[i]);
                    }
                }
#pragma unroll
                for (int d = 1; d <= 2; d <<= 1) {
#pragma unroll
                    for (int i = 0; i < 2; i++) {
                        r0[i] += __shfl_xor_sync(0xFFFFFFFFu, r0[i], d);
                        r1[i] += __shfl_xor_sync(0xFFFFFFFFu, r1[i], d);
                    }
                }
                if (t == 0) {
                    float* part = sPart + (wid >> 2) * 128;
#pragma unroll
                    for (int i = 0; i < 2; i++) {
                        part[mrow + 16 * i + g]     = r0[i];
                        part[mrow + 16 * i + g + 8] = r1[i];
                    }
                }
                __syncthreads();
                if (tid < TILE_M)
                    out[row_base + tid] = sPart[tid] + sPart[128 + tid] +
                                          sPart[256 + tid] + sPart[384 + tid] + sB6[0];
                __syncthreads();   // sPart/sA safe before next tile
            }
        }
    }
}

// ---------------------------------------------------------------------------
extern "C" void kernel_launch(void* const* d_in, const int* in_sizes, int n_in,
                              void* d_out, int out_size) {
    const float* coords = (const float*)d_in[0];
    const float* W1 = (const float*)d_in[1];
    const float* b1 = (const float*)d_in[2];
    const float* W2 = (const float*)d_in[3];
    const float* b2 = (const float*)d_in[4];
    const float* W3 = (const float*)d_in[5];
    const float* b3 = (const float*)d_in[6];
    const float* W4 = (const float*)d_in[7];
    const float* b4 = (const float*)d_in[8];
    const float* W5 = (const float*)d_in[9];
    const float* b5 = (const float*)d_in[10];
    const float* W6 = (const float*)d_in[11];
    const float* b6 = (const float*)d_in[12];
    float* out = (float*)d_out;

    const int n = in_sizes[0] / 2;      // rows
    const int ntiles = n / TILE_M;      // 4096

    int nsm = 148;
    cudaDeviceGetAttribute(&nsm, cudaDevAttrMultiProcessorCount, 0);
    const int grid = (nsm < ntiles) ? nsm : ntiles;

    transpose_w_kernel<<<dim3(NDIM / 32, KDIM / 32, 4), dim3(32, 8)>>>(W2, W3, W4, W5);

    cudaFuncSetAttribute(mlp_kernel, cudaFuncAttributeMaxDynamicSharedMemorySize, SMEM_TOTAL);
    mlp_kernel<<<grid, THREADS, SMEM_TOTAL>>>(coords, W1, b1, b2, b3, b4, b5,
                                              W6, b6, out, ntiles);
}

// round 15
// speedup vs baseline: 1.3815x; 1.3815x over previous
#include <cuda_runtime.h>
#include <cuda_fp16.h>
#include <cstdint>

// ---------------------------------------------------------------------------
// SmallMLP_INR: fused 6-layer MLP, base-target ISA (compute_103-safe).
// fp16 m16n8k16 mma.sync + ldmatrix, persistent CTAs (R13 win). NEW: A tile
// double-buffered + per-chunk release/acquire flags replace per-layer CTA
// barriers, letting warps skew so the HMMA issue cadence never pauses for
// epilogues. Warp = 128M x 32N; B = warp-private 2-slot cp.async ring.
// ---------------------------------------------------------------------------

#define THREADS 256
#define TILE_M  128
#define KDIM    256
#define NDIM    256

#define A_STRIDE 264       // halves; 528B rows -> ldmatrix conflict-free
#define SLOT_BYTES 4096    // 32 n-rows * 128B (64 k halves), XOR-swizzled
#define WARP_RING  8192    // 2 slots

// SMEM layout (bytes)
#define SM_W1    0
#define SM_B1    2048
#define SM_B2    3072
#define SM_B3    4096
#define SM_B4    5120
#define SM_B5    6144
#define SM_W6    7168
#define SM_B6    8192
#define SM_FLAGS 8208     // flagE[3][4] + rdDone[3] = 15 ints
#define SM_PART  8272     // 8*128 f32 = 4096
#define SM_A0    12416    // 128*264*2 = 67584
#define SM_A1    80000    // 67584
#define SM_RING  147584   // 8 warps * 8192 = 65536
#define SMEM_TOTAL 213120

// Pre-transposed fp16 weights: g_WtH[l][n*256 + k] = (half)W_{l+2}[k][n]
__device__ __half g_WtH[4][KDIM * NDIM];

// ---------------------------------------------------------------------------
__device__ __forceinline__ uint32_t smem_u32(const void* p) {
    uint32_t a;
    asm("{ .reg .u64 t; cvta.to.shared.u64 t, %1; cvt.u32.u64 %0, t; }" : "=r"(a) : "l"(p));
    return a;
}

__device__ __forceinline__ void mma_f16(float* c, const uint32_t* a, const uint32_t* b) {
    asm volatile(
        "mma.sync.aligned.m16n8k16.row.col.f32.f16.f16.f32 "
        "{%0,%1,%2,%3}, {%4,%5,%6,%7}, {%8,%9}, {%0,%1,%2,%3};\n"
        : "+f"(c[0]), "+f"(c[1]), "+f"(c[2]), "+f"(c[3])
        : "r"(a[0]), "r"(a[1]), "r"(a[2]), "r"(a[3]), "r"(b[0]), "r"(b[1]));
}

#define LDMATRIX_X4(r0, r1, r2, r3, addr) \
    asm volatile("ldmatrix.sync.aligned.m8n8.x4.shared.b16 {%0,%1,%2,%3}, [%4];" \
                 : "=r"(r0), "=r"(r1), "=r"(r2), "=r"(r3) : "r"(addr))

__device__ __forceinline__ void cp_async16(uint32_t dst, const void* src) {
    asm volatile("cp.async.cg.shared.global [%0], [%1], 16;" :: "r"(dst), "l"(src) : "memory");
}
__device__ __forceinline__ void cp_commit() { asm volatile("cp.async.commit_group;" ::: "memory"); }
__device__ __forceinline__ void cp_wait1()  { asm volatile("cp.async.wait_group 1;" ::: "memory"); }
__device__ __forceinline__ void cp_wait0()  { asm volatile("cp.async.wait_group 0;" ::: "memory"); }

// release/acquire flag ops (CTA scope, shared memory)
__device__ __forceinline__ int ld_acq(uint32_t a) {
    int v;
    asm volatile("ld.acquire.cta.shared.b32 %0, [%1];" : "=r"(v) : "r"(a) : "memory");
    return v;
}
__device__ __forceinline__ void red_rel(uint32_t a) {
    asm volatile("red.release.cta.shared.add.u32 [%0], %1;" :: "r"(a), "r"(1) : "memory");
}
__device__ __forceinline__ void spin_ge(uint32_t a, int target) {
    while (ld_acq(a) < target) { }
}

// Warp-private: one 32n x 64k B chunk (4KB) into a ring slot.
// Rows 128B, XOR-swizzled 16B segments: seg_phys = seg ^ (row & 7).
__device__ __forceinline__ void load_wchunk(uint32_t slot, const __half* Wt,
                                            int nbase, int c, int lid) {
    const uint32_t dst = slot + (uint32_t)lid * 128;
    const uint32_t rx = (uint32_t)(lid & 7);
    const __half* src = Wt + (size_t)(nbase + lid) * KDIM + c * 64;
#pragma unroll
    for (uint32_t j = 0; j < 8; j++)
        cp_async16(dst + ((j ^ rx) << 4), src + j * 8);
    cp_commit();
}

// ---------------------------------------------------------------------------
// weight pre-transpose + fp16 round
// ---------------------------------------------------------------------------
__global__ void transpose_w_kernel(const float* __restrict__ W2, const float* __restrict__ W3,
                                   const float* __restrict__ W4, const float* __restrict__ W5) {
    __shared__ float t[32][33];
    const float* W = (blockIdx.z == 0) ? W2 : (blockIdx.z == 1) ? W3
                   : (blockIdx.z == 2) ? W4 : W5;
    const int nb = blockIdx.x * 32, kb = blockIdx.y * 32;
    const int tx = threadIdx.x, ty = threadIdx.y;
#pragma unroll
    for (int i = 0; i < 32; i += 8)
        t[ty + i][tx] = W[(size_t)(kb + ty + i) * 256 + (nb + tx)];
    __syncthreads();
    __half* dst = g_WtH[blockIdx.z];
#pragma unroll
    for (int i = 0; i < 32; i += 8)
        dst[(size_t)(nb + ty + i) * 256 + (kb + tx)] = __float2half_rn(t[tx][ty + i]);
}

// ---------------------------------------------------------------------------
// main persistent kernel
// ---------------------------------------------------------------------------
__global__ void __launch_bounds__(THREADS, 1) mlp_kernel(
    const float* __restrict__ coords,
    const float* __restrict__ W1, const float* __restrict__ b1,
    const float* __restrict__ b2, const float* __restrict__ b3,
    const float* __restrict__ b4, const float* __restrict__ b5,
    const float* __restrict__ W6, const float* __restrict__ b6,
    float* __restrict__ out, int ntiles) {
    extern __shared__ __align__(128) char smem[];
    const uint32_t sb = smem_u32(smem);
    const int tid = threadIdx.x;
    const int wid = tid >> 5;
    const int lid = tid & 31;
    const int g = lid >> 2;
    const int t = lid & 3;
    const int nbase = wid * 32;      // this warp's private N slice

    float* sW1 = (float*)(smem + SM_W1);
    float* sB1 = (float*)(smem + SM_B1);
    float* sB2 = (float*)(smem + SM_B2);
    float* sB3 = (float*)(smem + SM_B3);
    float* sB4 = (float*)(smem + SM_B4);
    float* sB5 = (float*)(smem + SM_B5);
    float* sW6 = (float*)(smem + SM_W6);
    float* sB6 = (float*)(smem + SM_B6);
    float* sPart = (float*)(smem + SM_PART);
    __half* sA0 = (__half*)(smem + SM_A0);
    __half* sA1 = (__half*)(smem + SM_A1);
    const uint32_t fbase = sb + SM_FLAGS;           // flagE[3][4], rdDone[3]
    const uint32_t ring = sb + SM_RING + (uint32_t)wid * WARP_RING;

    // stage small params
    sW1[tid]       = W1[tid];
    sW1[tid + 256] = W1[tid + 256];
    sB1[tid] = b1[tid];
    sB2[tid] = b2[tid];
    sB3[tid] = b3[tid];
    sB4[tid] = b4[tid];
    sB5[tid] = b5[tid];
    sW6[tid] = W6[tid];
    if (tid == 0) sB6[0] = b6[0];

    // prologue: warp prefetches its chunks 0,1 of layer 2 (slots 0,1)
    load_wchunk(ring,              g_WtH[0], nbase, 0, lid);
    load_wchunk(ring + SLOT_BYTES, g_WtH[0], nbase, 1, lid);

    __syncthreads();

    // ldmatrix lane-address bases (A in both buffers, B in ring rows)
    const uint32_t aOff =
        (uint32_t)(((lid & 15) * A_STRIDE + ((lid & 16) ? 8 : 0)) * 2);
    const uint32_t aA0 = sb + SM_A0 + aOff;
    const uint32_t aA1 = sb + SM_A1 + aOff;
    const int brow = (lid & 7) + ((lid & 16) ? 8 : 0);
    const uint32_t bRow = (uint32_t)brow * 128;
    const uint32_t brx = (uint32_t)(brow & 7);
    const uint32_t b8 = (uint32_t)((lid >> 3) & 1);

    const int stride = gridDim.x;

#pragma unroll 1
    for (int tile = blockIdx.x; tile < ntiles; tile += stride) {
        const bool lastT = (tile + stride >= ntiles);
        const int row_base = tile * TILE_M;

        // reset flags (15 ints) — concurrent with layer-1 math, ordered by
        // the __syncthreads below
        if (tid < 15) *(int*)(smem + SM_FLAGS + tid * 4) = 0;

        // ---- Layer 1 (fan-in 2, FFMA) -> sA0 (fp16) ----
        {
            const int row = tid >> 1;
            const int j0  = (tid & 1) * 128;
            const float2 c = *(const float2*)(coords + 2 * (size_t)(row_base + row));
            __half* dst = sA0 + (size_t)row * A_STRIDE;
#pragma unroll
            for (int j = 0; j < 128; j += 2) {
                const int jj = j0 + j;
                float v0 = fmaxf(fmaf(c.x, sW1[jj + 0], fmaf(c.y, sW1[256 + jj + 0], sB1[jj + 0])), 0.f);
                float v1 = fmaxf(fmaf(c.x, sW1[jj + 1], fmaf(c.y, sW1[256 + jj + 1], sB1[jj + 1])), 0.f);
                *(__half2*)(dst + jj) = __floats2half2_rn(v0, v1);
            }
        }
        __syncthreads();

        // ---- Layers 2..5: flag-gated, warps skew freely ----
#pragma unroll 1
        for (int l = 0; l < 4; l++) {
            float acc[8][4][4];
#pragma unroll
            for (int i = 0; i < 8; i++)
#pragma unroll
                for (int j = 0; j < 4; j++)
#pragma unroll
                    for (int c = 0; c < 4; c++) acc[i][j][c] = 0.f;

            const uint32_t aA = (l & 1) ? aA1 : aA0;

#pragma unroll
            for (int c = 0; c < 4; c++) {
                const int f = l * 4 + c;

                // gate: A chunk c produced by warps 2c,2c+1's epilogue
                if (l > 0) spin_ge(fbase + (uint32_t)((l - 1) * 4 + c) * 4, 2);

                // B chunk f arrival (warp-private ring)
                if (lastT && f == 15) cp_wait0(); else cp_wait1();
                __syncwarp();

                const uint32_t slot = ring + (uint32_t)(f & 1) * SLOT_BYTES;
#pragma unroll
                for (int ks = 0; ks < 4; ks++) {
                    const int k0 = c * 64 + ks * 16;   // k offset in A (halves)
                    const uint32_t soff = ((((uint32_t)(2 * ks) + b8) ^ brx) << 4);
                    uint32_t b[2][4];
#pragma unroll
                    for (int np = 0; np < 2; np++)
                        LDMATRIX_X4(b[np][0], b[np][1], b[np][2], b[np][3],
                                    slot + bRow + (uint32_t)np * 2048 + soff);
#pragma unroll
                    for (int i = 0; i < 8; i++) {
                        uint32_t a[4];
                        LDMATRIX_X4(a[0], a[1], a[2], a[3],
                                    aA + (uint32_t)(i * 16 * A_STRIDE + k0) * 2);
#pragma unroll
                        for (int j = 0; j < 4; j++)
                            mma_f16(acc[i][j], a, &b[j >> 1][(j & 1) * 2]);
                    }
                }

                // prefetch flat chunk f+2 into the slot just consumed
                if (!(lastT && f >= 14)) {
                    const int q = f + 2;
                    load_wchunk(ring + (uint32_t)(q & 1) * SLOT_BYTES,
                                g_WtH[(q >> 2) & 3], nbase, q & 3, lid);
                }
            }

            // signal: this warp done reading buf[l&1] (layers 0,1 have waiters)
            if (l < 2 && lid == 0) red_rel(fbase + 48 + (uint32_t)l * 4);

            if (l < 3) {
                // WAR gate: buf[(l+1)&1] free once all warps read it in l-1
                if (l >= 1) spin_ge(fbase + 48 + (uint32_t)(l - 1) * 4, 8);

                // epilogue: buf[(l+1)&1] <- (half)relu(D + bias), cols [32w,32w+32)
                __half* sAW = ((l + 1) & 1) ? sA1 : sA0;
                const float* bias = (l == 0) ? sB2 : (l == 1) ? sB3 : sB4;
#pragma unroll
                for (int j = 0; j < 4; j++) {
                    const int col = nbase + 8 * j + 2 * t;
                    const float bs0 = bias[col], bs1 = bias[col + 1];
#pragma unroll
                    for (int i = 0; i < 8; i++) {
                        const int row = 16 * i + g;
                        *(__half2*)(sAW + (size_t)row * A_STRIDE + col) =
                            __floats2half2_rn(fmaxf(acc[i][j][0] + bs0, 0.f),
                                              fmaxf(acc[i][j][1] + bs1, 0.f));
                        *(__half2*)(sAW + (size_t)(row + 8) * A_STRIDE + col) =
                            __floats2half2_rn(fmaxf(acc[i][j][2] + bs0, 0.f),
                                              fmaxf(acc[i][j][3] + bs1, 0.f));
                    }
                }
                __syncwarp();
                // announce this warp's chunk contribution (release orders STS)
                if (lid == 0) red_rel(fbase + (uint32_t)(l * 4 + (wid >> 1)) * 4);
            } else {
                // ---- Layer 6: out = relu(D + b5) . W6 + b6 ----
                float r0[8], r1[8];
#pragma unroll
                for (int i = 0; i < 8; i++) { r0[i] = 0.f; r1[i] = 0.f; }
#pragma unroll
                for (int j = 0; j < 4; j++) {
                    const int col = nbase + 8 * j + 2 * t;
                    const float w0 = sW6[col], w1 = sW6[col + 1];
                    const float s0 = sB5[col], s1 = sB5[col + 1];
#pragma unroll
                    for (int i = 0; i < 8; i++) {
                        r0[i] = fmaf(fmaxf(acc[i][j][0] + s0, 0.f), w0, r0[i]);
                        r0[i] = fmaf(fmaxf(acc[i][j][1] + s1, 0.f), w1, r0[i]);
                        r1[i] = fmaf(fmaxf(acc[i][j][2] + s0, 0.f), w0, r1[i]);
                        r1[i] = fmaf(fmaxf(acc[i][j][3] + s1, 0.f), w1, r1[i]);
                    }
                }
#pragma unroll
                for (int d = 1; d <= 2; d <<= 1) {
#pragma unroll
                    for (int i = 0; i < 8; i++) {
                        r0[i] += __shfl_xor_sync(0xFFFFFFFFu, r0[i], d);
                        r1[i] += __shfl_xor_sync(0xFFFFFFFFu, r1[i], d);
                    }
                }
                if (t == 0) {
                    float* part = sPart + wid * 128;
#pragma unroll
                    for (int i = 0; i < 8; i++) {
                        part[16 * i + g]     = r0[i];
                        part[16 * i + g + 8] = r1[i];
                    }
                }
                __syncthreads();
                if (tid < TILE_M) {
                    float s = sB6[0];
#pragma unroll
                    for (int w = 0; w < 8; w++) s += sPart[w * 128 + tid];
                    out[row_base + tid] = s;
                }
                __syncthreads();   // tile end: flags/buffers safe to reuse
            }
        }
    }
}

// ---------------------------------------------------------------------------
extern "C" void kernel_launch(void* const* d_in, const int* in_sizes, int n_in,
                              void* d_out, int out_size) {
    const float* coords = (const float*)d_in[0];
    const float* W1 = (const float*)d_in[1];
    const float* b1 = (const float*)d_in[2];
    const float* W2 = (const float*)d_in[3];
    const float* b2 = (const float*)d_in[4];
    const float* W3 = (const float*)d_in[5];
    const float* b3 = (const float*)d_in[6];
    const float* W4 = (const float*)d_in[7];
    const float* b4 = (const float*)d_in[8];
    const float* W5 = (const float*)d_in[9];
    const float* b5 = (const float*)d_in[10];
    const float* W6 = (const float*)d_in[11];
    const float* b6 = (const float*)d_in[12];
    float* out = (float*)d_out;

    const int n = in_sizes[0] / 2;      // rows
    const int ntiles = n / TILE_M;      // 4096

    int nsm = 148;
    cudaDeviceGetAttribute(&nsm, cudaDevAttrMultiProcessorCount, 0);
    const int grid = (nsm < ntiles) ? nsm : ntiles;

    transpose_w_kernel<<<dim3(NDIM / 32, KDIM / 32, 4), dim3(32, 8)>>>(W2, W3, W4, W5);

    cudaFuncSetAttribute(mlp_kernel, cudaFuncAttributeMaxDynamicSharedMemorySize, SMEM_TOTAL);
    mlp_kernel<<<grid, THREADS, SMEM_TOTAL>>>(coords, W1, b1, b2, b3, b4, b5,
                                              W6, b6, out, ntiles);
}